// round 16
// baseline (speedup 1.0000x reference)
#include <cuda_runtime.h>
#include <cuda_fp16.h>
#include <math.h>
#include <stdint.h>

// ---------------- problem constants ----------------
#define BB      8
#define TT      4096
#define DD      512
#define QQ      4
#define KK_CB   1024
#define KER     5
#define TOUT    2048
#define NTOK    32768
#define NELEM   (NTOK * DD)              // 16777216
#define Y_SZ    (BB * TOUT * DD)         // 8388608
#define QO_SZ   NELEM
#define IDX_SZ  (QQ * NTOK)
#define LOSS_OFF (Y_SZ + QO_SZ + IDX_SZ)
#define MARGIN  8.0f
#define MTILE   112
#define NGRID   ((NTOK + MTILE - 1) / MTILE)   // 293

// ---------------- persistent scratch ----------------
__device__ float    g_residual[NELEM];              // exact fp32 residual
__device__ uint32_t g_r8[NELEM / 4];                // int8 residual, packed 4/word
__device__ uint32_t g_cb8[QQ * KK_CB * DD / 4];     // int8 codebooks
__device__ float    g_sr[NTOK];                     // per-token quant scale
__device__ float    g_sc[QQ * KK_CB];               // per-code quant scale
__device__ __half   g_dist16[(size_t)NTOK * KK_CB]; // approx distances (64 MB)
__device__ float    g_table[(size_t)KER * 4096 * DD]; // conv table (42 MB)
__device__ float    g_cnorm[QQ * KK_CB];
__device__ float    g_d1[NTOK];
__device__ int      g_idx[QQ * NTOK];
__device__ double   g_loss;

// ---------------- side stream for overlap ----------------
struct StreamInit {
    cudaStream_t s;
    cudaEvent_t e1, e2;
    StreamInit() {
        cudaStreamCreateWithFlags(&s, cudaStreamNonBlocking);
        cudaEventCreateWithFlags(&e1, cudaEventDisableTiming);
        cudaEventCreateWithFlags(&e2, cudaEventDisableTiming);
    }
};
static StreamInit g_si;

// ---------------- helpers ----------------
__device__ __forceinline__ uint32_t smem_u32(const void* p) {
    uint32_t a;
    asm("{ .reg .u64 t; cvta.to.shared.u64 t, %1; cvt.u32.u64 %0, t; }" : "=r"(a) : "l"(p));
    return a;
}
__device__ __forceinline__ void cp16(uint32_t s, const void* g) {
    asm volatile("cp.async.cg.shared.global [%0], [%1], 16;" :: "r"(s), "l"(g));
}
#define CP_COMMIT() asm volatile("cp.async.commit_group;" ::: "memory")
#define CP_WAIT0()  asm volatile("cp.async.wait_group 0;" ::: "memory")

__device__ __forceinline__ uint32_t pack4(float v0, float v1, float v2, float v3, float inv) {
    int a = __float2int_rn(v0 * inv), b = __float2int_rn(v1 * inv);
    int c = __float2int_rn(v2 * inv), d = __float2int_rn(v3 * inv);
    return (uint32_t)(a & 0xFF) | ((uint32_t)(b & 0xFF) << 8) |
           ((uint32_t)(c & 0xFF) << 16) | ((uint32_t)(d & 0xFF) << 24);
}

// ---------------- quantize codebooks + cnorm (+loss reset) ----------------
__global__ void quant_cb_kernel(const float* __restrict__ cb) {
    if (blockIdx.x == 0 && threadIdx.x == 0) g_loss = 0.0;
    int w    = (blockIdx.x * blockDim.x + threadIdx.x) >> 5;
    int lane = threadIdx.x & 31;
    if (w >= QQ * KK_CB) return;
    const float* c = cb + (size_t)w * DD;
    float rv[16];
    float nrm = 0.f, mx = 0.f;
    #pragma unroll
    for (int i = 0; i < 16; ++i) {
        float v = c[lane * 16 + i];
        rv[i] = v; nrm += v * v; mx = fmaxf(mx, fabsf(v));
    }
    #pragma unroll
    for (int o = 16; o > 0; o >>= 1) {
        nrm += __shfl_xor_sync(0xffffffffu, nrm, o);
        mx = fmaxf(mx, __shfl_xor_sync(0xffffffffu, mx, o));
    }
    float sc = fmaxf(mx, 1e-20f) / 127.0f;
    float inv = 1.0f / sc;
    uint4 pk;
    pk.x = pack4(rv[0],  rv[1],  rv[2],  rv[3],  inv);
    pk.y = pack4(rv[4],  rv[5],  rv[6],  rv[7],  inv);
    pk.z = pack4(rv[8],  rv[9],  rv[10], rv[11], inv);
    pk.w = pack4(rv[12], rv[13], rv[14], rv[15], inv);
    *(uint4*)(g_cb8 + (size_t)w * 128 + lane * 4) = pk;
    if (lane == 0) { g_cnorm[w] = nrm; g_sc[w] = sc; }
}

// ---------------- quantize x into r8 ----------------
__global__ void quant_x_kernel(const float* __restrict__ x) {
    int tok  = (blockIdx.x * blockDim.x + threadIdx.x) >> 5;
    int lane = threadIdx.x & 31;
    if (tok >= NTOK) return;
    const float* r = x + (size_t)tok * DD;
    float rv[16];
    float mx = 0.f;
    #pragma unroll
    for (int i = 0; i < 16; ++i) { rv[i] = r[lane * 16 + i]; mx = fmaxf(mx, fabsf(rv[i])); }
    #pragma unroll
    for (int o = 16; o > 0; o >>= 1) mx = fmaxf(mx, __shfl_xor_sync(0xffffffffu, mx, o));
    float sr = fmaxf(mx, 1e-20f) / 127.0f;
    float inv = 1.0f / sr;
    uint4 pk;
    pk.x = pack4(rv[0],  rv[1],  rv[2],  rv[3],  inv);
    pk.y = pack4(rv[4],  rv[5],  rv[6],  rv[7],  inv);
    pk.z = pack4(rv[8],  rv[9],  rv[10], rv[11], inv);
    pk.w = pack4(rv[12], rv[13], rv[14], rv[15], inv);
    *(uint4*)(g_r8 + (size_t)tok * 128 + lane * 4) = pk;
    if (lane == 0) g_sr[tok] = sr;
}

// ---------------- conv table GEMM (fp32, side stream) ----------------
__global__ __launch_bounds__(256)
void tableg_kernel(const float* __restrict__ cb,
                   const float* __restrict__ W) {
    __shared__ __align__(16) float As[16][132];
    __shared__ __align__(16) float Bs[16][132];

    int t  = threadIdx.x;
    int tx = t & 15, ty = t >> 4;
    int crow0 = blockIdx.x * 128;
    int ncol0 = blockIdx.y * 128;
    int kk    = blockIdx.z;

    const float* Wk = W + (size_t)kk * DD * DD;

    float acc[8][8];
    #pragma unroll
    for (int i = 0; i < 8; i++)
        #pragma unroll
        for (int j = 0; j < 8; j++) acc[i][j] = 0.f;

    for (int c0 = 0; c0 < DD; c0 += 16) {
        #pragma unroll
        for (int i = 0; i < 2; i++) {
            int idx = t + 256 * i;
            int r = idx >> 2, c = idx & 3;
            float4 va = *(const float4*)(cb + (size_t)(crow0 + r) * DD + c0 + 4 * c);
            As[4*c+0][r] = va.x; As[4*c+1][r] = va.y;
            As[4*c+2][r] = va.z; As[4*c+3][r] = va.w;
            int ci = idx >> 5, cq = idx & 31;
            float4 vb = *(const float4*)(Wk + (size_t)(c0 + ci) * DD + ncol0 + cq * 4);
            *(float4*)&Bs[ci][cq * 4] = vb;
        }
        __syncthreads();
        #pragma unroll
        for (int kki = 0; kki < 16; ++kki) {
            float a[8], b[8];
            *(float4*)(a)     = *(const float4*)&As[kki][ty * 8];
            *(float4*)(a + 4) = *(const float4*)&As[kki][ty * 8 + 4];
            *(float4*)(b)     = *(const float4*)&Bs[kki][tx * 8];
            *(float4*)(b + 4) = *(const float4*)&Bs[kki][tx * 8 + 4];
            #pragma unroll
            for (int i = 0; i < 8; i++)
                #pragma unroll
                for (int j = 0; j < 8; j++) acc[i][j] += a[i] * b[j];
        }
        __syncthreads();
    }
    #pragma unroll
    for (int i = 0; i < 8; i++) {
        int row = crow0 + ty * 8 + i;
        float* dst = g_table + ((size_t)kk * 4096 + row) * DD + ncol0 + tx * 8;
        *(float4*)(dst)     = make_float4(acc[i][0], acc[i][1], acc[i][2], acc[i][3]);
        *(float4*)(dst + 4) = make_float4(acc[i][4], acc[i][5], acc[i][6], acc[i][7]);
    }
}

// ---------------- int8 dp4a screen: 8x4 microtile, N-tile 64, occ 3 ----------------
// Layout: A[buf][half16][row(112)], B[buf][half16][row(64)]; tx owns codes tx+16*j (j<4).
__global__ __launch_bounds__(256, 3)
void screen_kernel(int stage) {
    __shared__ union {
        struct { __align__(16) uint4 A[2][4][MTILE]; __align__(16) uint4 B[2][4][64]; } tb;
        struct { float d[MTILE][17]; } red;
    } sm;

    int t  = threadIdx.x;
    int tx = t & 15, ty = t >> 4;
    int row0 = blockIdx.x * MTILE;
    bool act = (ty < 14);

    const uint32_t* __restrict__ Ab = g_r8;
    const uint32_t* __restrict__ Bb = g_cb8 + (size_t)stage * KK_CB * 128;
    const float*    __restrict__ cn = g_cnorm + stage * KK_CB;
    const float*    __restrict__ scs = g_sc + stage * KK_CB;

    uint32_t sA = smem_u32(&sm.tb.A[0][0][0]);
    uint32_t sB = smem_u32(&sm.tb.B[0][0][0]);

    int acc[8][4];
    #pragma unroll
    for (int i = 0; i < 8; i++)
        #pragma unroll
        for (int j = 0; j < 4; j++) acc[i][j] = 0;

    float d1[8];
    #pragma unroll
    for (int i = 0; i < 8; i++) d1[i] = 3.4e38f;

    // loader mapping:
    //   A: 448 uint4 per chunk -> idx t (all) and t+256 (t<192); idx = hh*112 + row
    //   B: 256 uint4 per chunk -> idx t; hh = t>>6, row = t&63
    int hhA0 = t / 112,          rowA0 = t - hhA0 * 112;
    int hhA1 = (t + 256) / 112,  rowA1 = (t + 256) - hhA1 * 112;
    bool a1v = (t < 192);
    int tokA0 = min(row0 + rowA0, NTOK - 1);
    int tokA1 = min(row0 + rowA1, NTOK - 1);
    int hhB = t >> 6, rowB = t & 63;

    // issue chunk ch (64 dims) into buffer ch&1
    #define ISSUE_CHUNK(ch) do { \
        int nt_ = (ch) >> 3, kc_ = (ch) & 7, b_ = (ch) & 1; \
        cp16(sA + (uint32_t)(((b_ * 4 + hhA0) * MTILE + rowA0) * 16), \
             Ab + (size_t)tokA0 * 128 + kc_ * 16 + hhA0 * 4); \
        if (a1v) cp16(sA + (uint32_t)(((b_ * 4 + hhA1) * MTILE + rowA1) * 16), \
                      Ab + (size_t)tokA1 * 128 + kc_ * 16 + hhA1 * 4); \
        cp16(sB + (uint32_t)(((b_ * 4 + hhB) * 64 + rowB) * 16), \
             Bb + (size_t)(nt_ * 64 + rowB) * 128 + kc_ * 16 + hhB * 4); \
        CP_COMMIT(); \
    } while (0)

    ISSUE_CHUNK(0);

    // 128 iterations: g = nt*8 + kc  (16 code tiles of 64 x 8 chunks of 64 dims)
    for (int g = 0; g < 128; ++g) {
        CP_WAIT0();
        __syncthreads();     // chunk g resident; other buffer drained
        int buf = g & 1;

        if (g < 127) ISSUE_CHUNK(g + 1);

        if (act) {
            #pragma unroll
            for (int h = 0; h < 4; ++h) {
                uint4 vb[4];
                #pragma unroll
                for (int j = 0; j < 4; j++) vb[j] = sm.tb.B[buf][h][tx + 16 * j];
                #pragma unroll
                for (int i = 0; i < 8; i++) {
                    uint4 va = sm.tb.A[buf][h][ty * 8 + i];
                    #pragma unroll
                    for (int j = 0; j < 4; j++) {
                        int s = acc[i][j];
                        s = __dp4a((int)va.x, (int)vb[j].x, s);
                        s = __dp4a((int)va.y, (int)vb[j].y, s);
                        s = __dp4a((int)va.z, (int)vb[j].z, s);
                        s = __dp4a((int)va.w, (int)vb[j].w, s);
                        acc[i][j] = s;
                    }
                }
            }

            if ((g & 7) == 7) {   // end of code tile: dists, fold min, reset
                int nt = g >> 3;
                int colb = nt * 64 + tx;
                float scf[4], cnf[4];
                #pragma unroll
                for (int j = 0; j < 4; j++) {
                    scf[j] = __ldg(scs + colb + 16 * j);
                    cnf[j] = __ldg(cn + colb + 16 * j);
                }
                #pragma unroll
                for (int i = 0; i < 8; i++) {
                    int row = row0 + ty * 8 + i;
                    float sri2 = 2.0f * __ldg(g_sr + min(row, NTOK - 1));
                    bool rok = (row < NTOK);
                    __half* dp = g_dist16 + (size_t)min(row, NTOK - 1) * KK_CB + colb;
                    #pragma unroll
                    for (int j = 0; j < 4; j++) {
                        float dd = cnf[j] - sri2 * scf[j] * (float)acc[i][j];
                        d1[i] = fminf(d1[i], dd);
                        acc[i][j] = 0;
                        if (rok) dp[16 * j] = __float2half(dd);
                    }
                }
            }
        }
    }
    #undef ISSUE_CHUNK

    __syncthreads();
    #pragma unroll
    for (int i = 0; i < 8; i++)
        if (act) sm.red.d[ty * 8 + i][tx] = d1[i];
    __syncthreads();
    if (t < MTILE) {
        float m = sm.red.d[t][0];
        #pragma unroll
        for (int j = 1; j < 16; j++) m = fminf(m, sm.red.d[t][j]);
        int tok = row0 + t;
        if (tok < NTOK) g_d1[tok] = m;
    }
}

// ---------------- fused rescue + residual update (lane-contiguous dims) ----------------
__global__ __launch_bounds__(256)
void rescue_update_kernel(const float* __restrict__ x,
                          const float* __restrict__ cb,
                          float* __restrict__ quant, int stage) {
    __shared__ float s_l[8];
    int warp = threadIdx.x >> 5, lane = threadIdx.x & 31;
    int tok  = blockIdx.x * 8 + warp;

    const __half* __restrict__ dist = g_dist16 + (size_t)tok * KK_CB;
    float thr = g_d1[tok] + MARGIN;

    const float* r = (stage == 0) ? (x + (size_t)tok * DD) : (g_residual + (size_t)tok * DD);
    float rv[16];
    #pragma unroll
    for (int i = 0; i < 4; ++i)
        *(float4*)(rv + 4 * i) = *(const float4*)(r + lane * 16 + 4 * i);

    const float* cbs = cb + (size_t)stage * KK_CB * DD;
    const float* cnp = g_cnorm + stage * KK_CB;

    float bd = 3.4e38f; int bk = 0;
    for (int j0 = 0; j0 < KK_CB; j0 += 32) {
        float dv = __half2float(dist[j0 + lane]);
        unsigned mask = __ballot_sync(0xffffffffu, dv <= thr);
        while (mask) {
            int j = j0 + __ffs(mask) - 1;
            mask &= mask - 1;
            const float* c = cbs + (size_t)j * DD + lane * 16;
            float s = 0.f;
            #pragma unroll
            for (int i = 0; i < 16; ++i) s += rv[i] * c[i];
            #pragma unroll
            for (int o = 16; o > 0; o >>= 1) s += __shfl_xor_sync(0xffffffffu, s, o);
            float de = __ldg(cnp + j) - 2.0f * s;
            if (de < bd) { bd = de; bk = j; }
        }
    }
    if (lane == 0) g_idx[stage * NTOK + tok] = bk;

    const float* c = cbs + (size_t)bk * DD + lane * 16;
    float nv[16];
    float lsum = 0.f, mx = 0.f;
    #pragma unroll
    for (int i = 0; i < 16; ++i) {
        nv[i] = rv[i] - c[i];
        lsum += nv[i] * nv[i];
        mx = fmaxf(mx, fabsf(nv[i]));
    }
    if (stage < QQ - 1) {
        float* res = g_residual + (size_t)tok * DD + lane * 16;
        #pragma unroll
        for (int i = 0; i < 4; ++i) *(float4*)(res + 4 * i) = *(float4*)(nv + 4 * i);
        #pragma unroll
        for (int o = 16; o > 0; o >>= 1) mx = fmaxf(mx, __shfl_xor_sync(0xffffffffu, mx, o));
        float sr = fmaxf(mx, 1e-20f) / 127.0f;
        float inv = 1.0f / sr;
        uint4 pk;
        pk.x = pack4(nv[0],  nv[1],  nv[2],  nv[3],  inv);
        pk.y = pack4(nv[4],  nv[5],  nv[6],  nv[7],  inv);
        pk.z = pack4(nv[8],  nv[9],  nv[10], nv[11], inv);
        pk.w = pack4(nv[12], nv[13], nv[14], nv[15], inv);
        *(uint4*)(g_r8 + (size_t)tok * 128 + lane * 4) = pk;
        if (lane == 0) g_sr[tok] = sr;
    } else {
        const float* xr = x + (size_t)tok * DD + lane * 16;
        float* q = quant + (size_t)tok * DD + lane * 16;
        #pragma unroll
        for (int i = 0; i < 16; ++i) q[i] = xr[i] - nv[i];
    }
    #pragma unroll
    for (int o = 16; o > 0; o >>= 1) lsum += __shfl_down_sync(0xffffffffu, lsum, o);
    if (lane == 0) s_l[warp] = lsum;
    __syncthreads();
    if (threadIdx.x == 0) {
        float s = 0.f;
        #pragma unroll
        for (int i = 0; i < 8; i++) s += s_l[i];
        atomicAdd(&g_loss, (double)s);
    }
}

// ---------------- gather + sum + GELU ----------------
__global__ __launch_bounds__(128)
void gather_gelu(float* __restrict__ y) {
    __shared__ int rows[20];
    int t = blockIdx.x;
    int b = t >> 11, to = t & (TOUT - 1);
    if (threadIdx.x < 20) {
        int kk = threadIdx.x >> 2, s = threadIdx.x & 3;
        int tin = 2 * to + kk - 1;
        rows[threadIdx.x] = ((unsigned)tin < (unsigned)TT)
            ? (kk * 4096 + s * 1024 + g_idx[s * NTOK + b * TT + tin]) : -1;
    }
    __syncthreads();
    int d4 = threadIdx.x;
    float ax = 0.f, ay = 0.f, az = 0.f, aw = 0.f;
    #pragma unroll
    for (int j = 0; j < 20; j++) {
        int r = rows[j];
        if (r >= 0) {
            float4 v = *(const float4*)(g_table + (size_t)r * DD + d4 * 4);
            ax += v.x; ay += v.y; az += v.z; aw += v.w;
        }
    }
    float4 o;
    o.x = 0.5f * ax * (1.0f + erff(ax * 0.70710678118654752f));
    o.y = 0.5f * ay * (1.0f + erff(ay * 0.70710678118654752f));
    o.z = 0.5f * az * (1.0f + erff(az * 0.70710678118654752f));
    o.w = 0.5f * aw * (1.0f + erff(aw * 0.70710678118654752f));
    *(float4*)(y + (size_t)t * DD + d4 * 4) = o;
}

// ---------------- indices (as float) + loss ----------------
__global__ void finalize_kernel(float* __restrict__ out) {
    int i = blockIdx.x * blockDim.x + threadIdx.x;
    if (i < IDX_SZ) out[Y_SZ + QO_SZ + i] = (float)g_idx[i];
    if (i == 0)     out[LOSS_OFF] = (float)(0.25 * g_loss / (double)NELEM);
}

// ---------------- launch ----------------
extern "C" void kernel_launch(void* const* d_in, const int* in_sizes, int n_in,
                              void* d_out, int out_size) {
    const float* x  = (const float*)d_in[0];
    const float* cb = (const float*)d_in[1];
    const float* w  = (const float*)d_in[2];
    float* out   = (float*)d_out;
    float* y     = out;
    float* quant = out + Y_SZ;

    // fork: tableg on side stream
    cudaEventRecord(g_si.e1, 0);
    cudaStreamWaitEvent(g_si.s, g_si.e1, 0);
    tableg_kernel<<<dim3(32, 4, 5), 256, 0, g_si.s>>>(cb, w);
    cudaEventRecord(g_si.e2, g_si.s);

    // main stream: VQ chain
    quant_cb_kernel<<<(QQ * KK_CB * 32 + 255) / 256, 256>>>(cb);
    quant_x_kernel<<<(NTOK * 32 + 255) / 256, 256>>>(x);
    for (int s = 0; s < QQ; ++s) {
        screen_kernel<<<NGRID, 256>>>(s);
        rescue_update_kernel<<<NTOK / 8, 256>>>(x, cb, quant, s);
    }

    // join: gather needs both the table and all indices
    cudaStreamWaitEvent(0, g_si.e2, 0);
    gather_gelu<<<BB * TOUT, 128>>>(y);
    finalize_kernel<<<(IDX_SZ + 255) / 256, 256>>>(out);
}

// round 17
// speedup vs baseline: 1.1809x; 1.1809x over previous
#include <cuda_runtime.h>
#include <cuda_fp16.h>
#include <math.h>
#include <stdint.h>

// ---------------- problem constants ----------------
#define BB      8
#define TT      4096
#define DD      512
#define QQ      4
#define KK_CB   1024
#define KER     5
#define TOUT    2048
#define NTOK    32768
#define NELEM   (NTOK * DD)              // 16777216
#define Y_SZ    (BB * TOUT * DD)         // 8388608
#define QO_SZ   NELEM
#define IDX_SZ  (QQ * NTOK)
#define LOSS_OFF (Y_SZ + QO_SZ + IDX_SZ)
#define MARGIN  8.0f
#define MTILE   112
#define NGRID   ((NTOK + MTILE - 1) / MTILE)   // 293

// ---------------- persistent scratch ----------------
__device__ float    g_residual[NELEM];              // exact fp32 residual
__device__ uint32_t g_r8[NELEM / 4];                // int8 residual, packed 4/word
__device__ uint32_t g_cb8[QQ * KK_CB * DD / 4];     // int8 codebooks
__device__ float    g_sr[NTOK];                     // per-token quant scale
__device__ float    g_sc[QQ * KK_CB];               // per-code quant scale
__device__ __half   g_dist16[(size_t)NTOK * KK_CB]; // approx distances (64 MB)
__device__ float    g_table[(size_t)KER * 4096 * DD]; // conv table (42 MB)
__device__ float    g_cnorm[QQ * KK_CB];
__device__ float    g_d1[NTOK];
__device__ int      g_idx[QQ * NTOK];
__device__ double   g_loss;

// ---------------- side stream for overlap ----------------
struct StreamInit {
    cudaStream_t s;
    cudaEvent_t e1, e2;
    StreamInit() {
        cudaStreamCreateWithFlags(&s, cudaStreamNonBlocking);
        cudaEventCreateWithFlags(&e1, cudaEventDisableTiming);
        cudaEventCreateWithFlags(&e2, cudaEventDisableTiming);
    }
};
static StreamInit g_si;

// ---------------- helpers ----------------
__device__ __forceinline__ uint32_t smem_u32(const void* p) {
    uint32_t a;
    asm("{ .reg .u64 t; cvta.to.shared.u64 t, %1; cvt.u32.u64 %0, t; }" : "=r"(a) : "l"(p));
    return a;
}
__device__ __forceinline__ void cp16(uint32_t s, const void* g) {
    asm volatile("cp.async.cg.shared.global [%0], [%1], 16;" :: "r"(s), "l"(g));
}
#define CP_COMMIT() asm volatile("cp.async.commit_group;" ::: "memory")
#define CP_WAIT0()  asm volatile("cp.async.wait_group 0;" ::: "memory")

__device__ __forceinline__ uint32_t pack4(float v0, float v1, float v2, float v3, float inv) {
    int a = __float2int_rn(v0 * inv), b = __float2int_rn(v1 * inv);
    int c = __float2int_rn(v2 * inv), d = __float2int_rn(v3 * inv);
    return (uint32_t)(a & 0xFF) | ((uint32_t)(b & 0xFF) << 8) |
           ((uint32_t)(c & 0xFF) << 16) | ((uint32_t)(d & 0xFF) << 24);
}

// ---------------- quantize codebooks + cnorm (+loss reset) ----------------
__global__ void quant_cb_kernel(const float* __restrict__ cb) {
    if (blockIdx.x == 0 && threadIdx.x == 0) g_loss = 0.0;
    int w    = (blockIdx.x * blockDim.x + threadIdx.x) >> 5;
    int lane = threadIdx.x & 31;
    if (w >= QQ * KK_CB) return;
    const float* c = cb + (size_t)w * DD;
    float rv[16];
    float nrm = 0.f, mx = 0.f;
    #pragma unroll
    for (int i = 0; i < 16; ++i) {
        float v = c[lane * 16 + i];
        rv[i] = v; nrm += v * v; mx = fmaxf(mx, fabsf(v));
    }
    #pragma unroll
    for (int o = 16; o > 0; o >>= 1) {
        nrm += __shfl_xor_sync(0xffffffffu, nrm, o);
        mx = fmaxf(mx, __shfl_xor_sync(0xffffffffu, mx, o));
    }
    float sc = fmaxf(mx, 1e-20f) / 127.0f;
    float inv = 1.0f / sc;
    uint4 pk;
    pk.x = pack4(rv[0],  rv[1],  rv[2],  rv[3],  inv);
    pk.y = pack4(rv[4],  rv[5],  rv[6],  rv[7],  inv);
    pk.z = pack4(rv[8],  rv[9],  rv[10], rv[11], inv);
    pk.w = pack4(rv[12], rv[13], rv[14], rv[15], inv);
    *(uint4*)(g_cb8 + (size_t)w * 128 + lane * 4) = pk;
    if (lane == 0) { g_cnorm[w] = nrm; g_sc[w] = sc; }
}

// ---------------- quantize x into r8 ----------------
__global__ void quant_x_kernel(const float* __restrict__ x) {
    int tok  = (blockIdx.x * blockDim.x + threadIdx.x) >> 5;
    int lane = threadIdx.x & 31;
    if (tok >= NTOK) return;
    const float* r = x + (size_t)tok * DD;
    float rv[16];
    float mx = 0.f;
    #pragma unroll
    for (int i = 0; i < 16; ++i) { rv[i] = r[lane * 16 + i]; mx = fmaxf(mx, fabsf(rv[i])); }
    #pragma unroll
    for (int o = 16; o > 0; o >>= 1) mx = fmaxf(mx, __shfl_xor_sync(0xffffffffu, mx, o));
    float sr = fmaxf(mx, 1e-20f) / 127.0f;
    float inv = 1.0f / sr;
    uint4 pk;
    pk.x = pack4(rv[0],  rv[1],  rv[2],  rv[3],  inv);
    pk.y = pack4(rv[4],  rv[5],  rv[6],  rv[7],  inv);
    pk.z = pack4(rv[8],  rv[9],  rv[10], rv[11], inv);
    pk.w = pack4(rv[12], rv[13], rv[14], rv[15], inv);
    *(uint4*)(g_r8 + (size_t)tok * 128 + lane * 4) = pk;
    if (lane == 0) g_sr[tok] = sr;
}

// ---------------- conv table GEMM (fp32, side stream) ----------------
__global__ __launch_bounds__(256)
void tableg_kernel(const float* __restrict__ cb,
                   const float* __restrict__ W) {
    __shared__ __align__(16) float As[16][132];
    __shared__ __align__(16) float Bs[16][132];

    int t  = threadIdx.x;
    int tx = t & 15, ty = t >> 4;
    int crow0 = blockIdx.x * 128;
    int ncol0 = blockIdx.y * 128;
    int kk    = blockIdx.z;

    const float* Wk = W + (size_t)kk * DD * DD;

    float acc[8][8];
    #pragma unroll
    for (int i = 0; i < 8; i++)
        #pragma unroll
        for (int j = 0; j < 8; j++) acc[i][j] = 0.f;

    for (int c0 = 0; c0 < DD; c0 += 16) {
        #pragma unroll
        for (int i = 0; i < 2; i++) {
            int idx = t + 256 * i;
            int r = idx >> 2, c = idx & 3;
            float4 va = *(const float4*)(cb + (size_t)(crow0 + r) * DD + c0 + 4 * c);
            As[4*c+0][r] = va.x; As[4*c+1][r] = va.y;
            As[4*c+2][r] = va.z; As[4*c+3][r] = va.w;
            int ci = idx >> 5, cq = idx & 31;
            float4 vb = *(const float4*)(Wk + (size_t)(c0 + ci) * DD + ncol0 + cq * 4);
            *(float4*)&Bs[ci][cq * 4] = vb;
        }
        __syncthreads();
        #pragma unroll
        for (int kki = 0; kki < 16; ++kki) {
            float a[8], b[8];
            *(float4*)(a)     = *(const float4*)&As[kki][ty * 8];
            *(float4*)(a + 4) = *(const float4*)&As[kki][ty * 8 + 4];
            *(float4*)(b)     = *(const float4*)&Bs[kki][tx * 8];
            *(float4*)(b + 4) = *(const float4*)&Bs[kki][tx * 8 + 4];
            #pragma unroll
            for (int i = 0; i < 8; i++)
                #pragma unroll
                for (int j = 0; j < 8; j++) acc[i][j] += a[i] * b[j];
        }
        __syncthreads();
    }
    #pragma unroll
    for (int i = 0; i < 8; i++) {
        int row = crow0 + ty * 8 + i;
        float* dst = g_table + ((size_t)kk * 4096 + row) * DD + ncol0 + tx * 8;
        *(float4*)(dst)     = make_float4(acc[i][0], acc[i][1], acc[i][2], acc[i][3]);
        *(float4*)(dst + 4) = make_float4(acc[i][4], acc[i][5], acc[i][6], acc[i][7]);
    }
}

// ---------------- int8 dp4a screen (R13 best config: K-chunk 32, double buffer) ----------------
// Layout: A[buf][half16][row], B[buf][half16][row]; thread tx owns codes tx+16*j.
__global__ __launch_bounds__(256, 2)
void screen_kernel(int stage) {
    __shared__ union {
        struct { __align__(16) uint4 A[2][2][MTILE]; __align__(16) uint4 B[2][2][128]; } tb;
        struct { float d[MTILE][17]; } red;
    } sm;

    int t  = threadIdx.x;
    int tx = t & 15, ty = t >> 4;
    int row0 = blockIdx.x * MTILE;
    bool act = (ty < 14);

    const uint32_t* __restrict__ Ab = g_r8;
    const uint32_t* __restrict__ Bb = g_cb8 + (size_t)stage * KK_CB * 128;
    const float*    __restrict__ cn = g_cnorm + stage * KK_CB;
    const float*    __restrict__ scs = g_sc + stage * KK_CB;

    uint32_t sA = smem_u32(&sm.tb.A[0][0][0]);
    uint32_t sB = smem_u32(&sm.tb.B[0][0][0]);

    int acc[8][8];
    #pragma unroll
    for (int i = 0; i < 8; i++)
        #pragma unroll
        for (int j = 0; j < 8; j++) acc[i][j] = 0;

    float d1[8];
    #pragma unroll
    for (int i = 0; i < 8; i++) d1[i] = 3.4e38f;

    // loader mapping: row = t>>1 (0..127), h = t&1
    int lrow = t >> 1, lh = t & 1;
    bool aval = (lrow < MTILE);
    int tokA = min(row0 + (aval ? lrow : 0), NTOK - 1);

    // prologue: chunk 0 (nt=0, kc=0) into buffer 0
    if (aval) cp16(sA + (uint32_t)((lh * MTILE + lrow) * 16),
                   Ab + (size_t)tokA * 128 + lh * 4);
    cp16(sB + (uint32_t)((lh * 128 + lrow) * 16),
         Bb + (size_t)lrow * 128 + lh * 4);
    CP_COMMIT();

    for (int g = 0; g < 128; ++g) {
        CP_WAIT0();
        __syncthreads();     // buf[g&1] complete and visible; other buf drained
        int buf = g & 1;

        if (g < 127) {       // issue async loads for chunk g+1 into the other buffer
            int ng = g + 1;
            int nt = ng >> 4, kc = ng & 15;
            int nb = ng & 1;
            if (aval) cp16(sA + (uint32_t)(((nb * 2 + lh) * MTILE + lrow) * 16),
                           Ab + (size_t)tokA * 128 + kc * 8 + lh * 4);
            cp16(sB + (uint32_t)(((nb * 2 + lh) * 128 + lrow) * 16),
                 Bb + (size_t)(nt * 128 + lrow) * 128 + kc * 8 + lh * 4);
            CP_COMMIT();
        }

        if (act) {
            #pragma unroll
            for (int h = 0; h < 2; ++h) {
                uint4 vb[8];
                #pragma unroll
                for (int j = 0; j < 8; j++) vb[j] = sm.tb.B[buf][h][tx + 16 * j];
                #pragma unroll
                for (int i = 0; i < 8; i++) {
                    uint4 va = sm.tb.A[buf][h][ty * 8 + i];
                    #pragma unroll
                    for (int j = 0; j < 8; j++) {
                        int s = acc[i][j];
                        s = __dp4a((int)va.x, (int)vb[j].x, s);
                        s = __dp4a((int)va.y, (int)vb[j].y, s);
                        s = __dp4a((int)va.z, (int)vb[j].z, s);
                        s = __dp4a((int)va.w, (int)vb[j].w, s);
                        acc[i][j] = s;
                    }
                }
            }

            if ((g & 15) == 15) {   // end of code tile: dists, fold min, reset
                int nt = g >> 4;
                int colb = nt * 128 + tx;
                float scf[8], cnf[8];
                #pragma unroll
                for (int j = 0; j < 8; j++) {
                    scf[j] = __ldg(scs + colb + 16 * j);
                    cnf[j] = __ldg(cn + colb + 16 * j);
                }
                #pragma unroll
                for (int i = 0; i < 8; i++) {
                    int row = row0 + ty * 8 + i;
                    float sri2 = 2.0f * __ldg(g_sr + min(row, NTOK - 1));
                    bool rok = (row < NTOK);
                    __half* dp = g_dist16 + (size_t)min(row, NTOK - 1) * KK_CB + colb;
                    #pragma unroll
                    for (int j = 0; j < 8; j++) {
                        float dd = cnf[j] - sri2 * scf[j] * (float)acc[i][j];
                        d1[i] = fminf(d1[i], dd);
                        acc[i][j] = 0;
                        if (rok) dp[16 * j] = __float2half(dd);
                    }
                }
            }
        }
    }

    __syncthreads();
    #pragma unroll
    for (int i = 0; i < 8; i++)
        if (act) sm.red.d[ty * 8 + i][tx] = d1[i];
    __syncthreads();
    if (t < MTILE) {
        float m = sm.red.d[t][0];
        #pragma unroll
        for (int j = 1; j < 16; j++) m = fminf(m, sm.red.d[t][j]);
        int tok = row0 + t;
        if (tok < NTOK) g_d1[tok] = m;
    }
}

// ---------------- fused rescue + residual update, vectorized dist scan ----------------
__global__ __launch_bounds__(256)
void rescue_update_kernel(const float* __restrict__ x,
                          const float* __restrict__ cb,
                          float* __restrict__ quant, int stage) {
    __shared__ float s_l[8];
    int warp = threadIdx.x >> 5, lane = threadIdx.x & 31;
    int tok  = blockIdx.x * 8 + warp;

    const __half* __restrict__ dist = g_dist16 + (size_t)tok * KK_CB;
    float thr = g_d1[tok] + MARGIN;

    const float* r = (stage == 0) ? (x + (size_t)tok * DD) : (g_residual + (size_t)tok * DD);
    float rv[16];
    #pragma unroll
    for (int i = 0; i < 4; ++i)
        *(float4*)(rv + 4 * i) = *(const float4*)(r + lane * 16 + 4 * i);

    const float* cbs = cb + (size_t)stage * KK_CB * DD;
    const float* cnp = g_cnorm + stage * KK_CB;

    float bd = 3.4e38f; int bk = 0;
    // vectorized scan: each lane owns 8 consecutive dists per block of 256
    #pragma unroll
    for (int j0 = 0; j0 < KK_CB; j0 += 256) {
        uint4 pk = *(const uint4*)(dist + j0 + lane * 8);
        const half2* h2 = (const half2*)&pk;
        int lm = 0;
        #pragma unroll
        for (int q = 0; q < 4; ++q) {
            float2 f = __half22float2(h2[q]);
            if (f.x <= thr) lm |= 1 << (2 * q);
            if (f.y <= thr) lm |= 1 << (2 * q + 1);
        }
        unsigned actm = __ballot_sync(0xffffffffu, lm != 0);
        while (actm) {
            int L = __ffs(actm) - 1;
            actm &= actm - 1;
            int bm = __shfl_sync(0xffffffffu, lm, L);
            while (bm) {
                int b = __ffs(bm) - 1;
                bm &= bm - 1;
                int j = j0 + L * 8 + b;           // ascending j order preserved
                const float* c = cbs + (size_t)j * DD + lane * 16;
                float s = 0.f;
                #pragma unroll
                for (int i = 0; i < 16; ++i) s += rv[i] * c[i];
                #pragma unroll
                for (int o = 16; o > 0; o >>= 1) s += __shfl_xor_sync(0xffffffffu, s, o);
                float de = __ldg(cnp + j) - 2.0f * s;
                if (de < bd) { bd = de; bk = j; }
            }
        }
    }
    if (lane == 0) g_idx[stage * NTOK + tok] = bk;

    const float* c = cbs + (size_t)bk * DD + lane * 16;
    float nv[16];
    float lsum = 0.f, mx = 0.f;
    #pragma unroll
    for (int i = 0; i < 16; ++i) {
        nv[i] = rv[i] - c[i];
        lsum += nv[i] * nv[i];
        mx = fmaxf(mx, fabsf(nv[i]));
    }
    if (stage < QQ - 1) {
        float* res = g_residual + (size_t)tok * DD + lane * 16;
        #pragma unroll
        for (int i = 0; i < 4; ++i) *(float4*)(res + 4 * i) = *(float4*)(nv + 4 * i);
        #pragma unroll
        for (int o = 16; o > 0; o >>= 1) mx = fmaxf(mx, __shfl_xor_sync(0xffffffffu, mx, o));
        float sr = fmaxf(mx, 1e-20f) / 127.0f;
        float inv = 1.0f / sr;
        uint4 pk;
        pk.x = pack4(nv[0],  nv[1],  nv[2],  nv[3],  inv);
        pk.y = pack4(nv[4],  nv[5],  nv[6],  nv[7],  inv);
        pk.z = pack4(nv[8],  nv[9],  nv[10], nv[11], inv);
        pk.w = pack4(nv[12], nv[13], nv[14], nv[15], inv);
        *(uint4*)(g_r8 + (size_t)tok * 128 + lane * 4) = pk;
        if (lane == 0) g_sr[tok] = sr;
    } else {
        const float* xr = x + (size_t)tok * DD + lane * 16;
        float* q = quant + (size_t)tok * DD + lane * 16;
        #pragma unroll
        for (int i = 0; i < 16; ++i) q[i] = xr[i] - nv[i];
    }
    #pragma unroll
    for (int o = 16; o > 0; o >>= 1) lsum += __shfl_down_sync(0xffffffffu, lsum, o);
    if (lane == 0) s_l[warp] = lsum;
    __syncthreads();
    if (threadIdx.x == 0) {
        float s = 0.f;
        #pragma unroll
        for (int i = 0; i < 8; i++) s += s_l[i];
        atomicAdd(&g_loss, (double)s);
    }
}

// ---------------- gather + sum + GELU ----------------
__global__ __launch_bounds__(128)
void gather_gelu(float* __restrict__ y) {
    __shared__ int rows[20];
    int t = blockIdx.x;
    int b = t >> 11, to = t & (TOUT - 1);
    if (threadIdx.x < 20) {
        int kk = threadIdx.x >> 2, s = threadIdx.x & 3;
        int tin = 2 * to + kk - 1;
        rows[threadIdx.x] = ((unsigned)tin < (unsigned)TT)
            ? (kk * 4096 + s * 1024 + g_idx[s * NTOK + b * TT + tin]) : -1;
    }
    __syncthreads();
    int d4 = threadIdx.x;
    float ax = 0.f, ay = 0.f, az = 0.f, aw = 0.f;
    #pragma unroll
    for (int j = 0; j < 20; j++) {
        int r = rows[j];
        if (r >= 0) {
            float4 v = *(const float4*)(g_table + (size_t)r * DD + d4 * 4);
            ax += v.x; ay += v.y; az += v.z; aw += v.w;
        }
    }
    float4 o;
    o.x = 0.5f * ax * (1.0f + erff(ax * 0.70710678118654752f));
    o.y = 0.5f * ay * (1.0f + erff(ay * 0.70710678118654752f));
    o.z = 0.5f * az * (1.0f + erff(az * 0.70710678118654752f));
    o.w = 0.5f * aw * (1.0f + erff(aw * 0.70710678118654752f));
    *(float4*)(y + (size_t)t * DD + d4 * 4) = o;
}

// ---------------- indices (as float) + loss ----------------
__global__ void finalize_kernel(float* __restrict__ out) {
    int i = blockIdx.x * blockDim.x + threadIdx.x;
    if (i < IDX_SZ) out[Y_SZ + QO_SZ + i] = (float)g_idx[i];
    if (i == 0)     out[LOSS_OFF] = (float)(0.25 * g_loss / (double)NELEM);
}

// ---------------- launch ----------------
extern "C" void kernel_launch(void* const* d_in, const int* in_sizes, int n_in,
                              void* d_out, int out_size) {
    const float* x  = (const float*)d_in[0];
    const float* cb = (const float*)d_in[1];
    const float* w  = (const float*)d_in[2];
    float* out   = (float*)d_out;
    float* y     = out;
    float* quant = out + Y_SZ;

    // fork: tableg on side stream
    cudaEventRecord(g_si.e1, 0);
    cudaStreamWaitEvent(g_si.s, g_si.e1, 0);
    tableg_kernel<<<dim3(32, 4, 5), 256, 0, g_si.s>>>(cb, w);
    cudaEventRecord(g_si.e2, g_si.s);

    // main stream: VQ chain
    quant_cb_kernel<<<(QQ * KK_CB * 32 + 255) / 256, 256>>>(cb);
    quant_x_kernel<<<(NTOK * 32 + 255) / 256, 256>>>(x);
    for (int s = 0; s < QQ; ++s) {
        screen_kernel<<<NGRID, 256>>>(s);
        rescue_update_kernel<<<NTOK / 8, 256>>>(x, cb, quant, s);
    }

    // join: gather needs both the table and all indices
    cudaStreamWaitEvent(0, g_si.e2, 0);
    gather_gelu<<<BB * TOUT, 128>>>(y);
    finalize_kernel<<<(IDX_SZ + 255) / 256, 256>>>(out);
}